// round 8
// baseline (speedup 1.0000x reference)
#include <cuda_runtime.h>
#include <cstdint>

// ---------------------------------------------------------------------------
// HT model via split-tf32 mma.sync, 3-stage cp.async pipeline (1 barrier/stage).
//   C[j][m,n] = act( sum_k Aop[j][m,k] * W[j][n,k or k,n] + bias[n] )
// Aop = A1 rows or fused pair-product A1*A1[+aOff2] (tree levels, PROD).
// smem: pad-20 linear layout (80B row stride) -> conflict-free cp.async
// stores AND fragment LDS with compile-time immediate offsets.
// tf32 split x = hi + lo in registers; 3 MMAs (hi*hi + hi*lo + lo*hi) per
// m16n8k8 product into fp32 accumulators (~2^-21 error/GEMM, budget 1e-3).
// CTA tile 128x64, BK=16, 8 warps (4x2), warp tile 32x32.
// ---------------------------------------------------------------------------

__device__ float g_h1[262144L * 128];
__device__ float g_bufA[262144L * 64];
__device__ float g_bufB[262144L * 64];

static __device__ __forceinline__ uint32_t smem_u32(const void* p) {
    uint32_t a;
    asm("{ .reg .u64 t; cvta.to.shared.u64 t, %1; cvt.u32.u64 %0, t; }" : "=r"(a) : "l"(p));
    return a;
}
static __device__ __forceinline__ void cp16(uint32_t dst, const void* src) {
    asm volatile("cp.async.ca.shared.global [%0], [%1], 16;" :: "r"(dst), "l"(src));
}
static __device__ __forceinline__ void cp4(uint32_t dst, const void* src) {
    asm volatile("cp.async.ca.shared.global [%0], [%1], 4;" :: "r"(dst), "l"(src));
}
#define CP_COMMIT() asm volatile("cp.async.commit_group;" ::: "memory")
#define CP_WAIT1()  asm volatile("cp.async.wait_group 1;" ::: "memory")
#define CP_WAIT0()  asm volatile("cp.async.wait_group 0;" ::: "memory")

static __device__ __forceinline__ float tf32_hi(float x) {
    uint32_t h;
    asm("cvt.rna.tf32.f32 %0, %1;" : "=r"(h) : "f"(x));
    return __uint_as_float(h);
}

#define MMA_TF32(d, a, b)                                                     \
    asm volatile(                                                             \
        "mma.sync.aligned.m16n8k8.row.col.f32.tf32.tf32.f32 "                 \
        "{%0,%1,%2,%3}, {%4,%5,%6,%7}, {%8,%9}, {%0,%1,%2,%3};"               \
        : "+f"((d)[0]), "+f"((d)[1]), "+f"((d)[2]), "+f"((d)[3])              \
        : "r"((a)[0]), "r"((a)[1]), "r"((a)[2]), "r"((a)[3]),                 \
          "r"((b)[0]), "r"((b)[1]))

template <int KDIM, bool PROD, bool WT, bool RELU>
__global__ void __launch_bounds__(256, 2) mma_gemm(
    const float* __restrict__ A1base, long ldA, long jStrideA, int aOff2,
    const float* __restrict__ Wbase, long jStrideW,
    const float* __restrict__ bias,
    float* __restrict__ Cbase, long ldC, long jStrideC,
    int Ndim)
{
    extern __shared__ float sm[];
    constexpr int NST  = KDIM / 16;
    constexpr int AODD = 2560;                    // odd-row tile (PROD only)
    constexpr int BOFF = PROD ? 5120 : 2560;
    constexpr int STG  = PROD ? 6400 : 3840;      // floats per stage

    const int j = blockIdx.z;
    const float* A1 = A1base + (long)j * jStrideA;
    const float* W  = Wbase  + (long)j * jStrideW;
    float* C        = Cbase  + (long)j * jStrideC;
    const int m0 = blockIdx.x * 128;
    const int n0 = blockIdx.y * 64;

    const int tid = threadIdx.x;
    const int wid = tid >> 5, lid = tid & 31;
    const int wm = wid >> 1, wn = wid & 1;     // warps: 4 along M x 2 along N
    const int g = lid >> 2, tig = lid & 3;

    const uint32_t smb = smem_u32(sm);

    // ---- per-thread source pointers (advanced by 16 floats per stage) ----
    const int ar = tid & 127;          // A row
    const int ac = tid >> 7;           // chunks ac*4 and ac*4+8
    const float* aS = A1 + (long)(m0 + ar) * ldA + ac * 4;
    const uint32_t aD = smb + (uint32_t)(ar * 20 + ac * 4) * 4;

    const float* wS = nullptr;         // WT path
    uint32_t bD = 0;
    const float* wN = nullptr;         // non-WT path
    uint32_t bD4 = 0;
    if (WT) {
        const int brow = tid & 63, bc = tid >> 6;
        int n = n0 + brow; if (n >= Ndim) n = Ndim - 1;
        wS = W + (long)n * KDIM + bc * 4;
        bD = smb + (uint32_t)(BOFF + brow * 20 + bc * 4) * 4;
    } else {
        const int brow = tid >> 2, k0 = (tid & 3) * 4;
        int n = n0 + brow; if (n >= Ndim) n = Ndim - 1;
        wN = W + (long)k0 * Ndim + n;
        bD4 = smb + (uint32_t)(BOFF + brow * 20 + k0) * 4;
    }

    auto issue = [&](int buf) {
        const uint32_t off = (uint32_t)buf * (STG * 4);
        cp16(aD + off, aS);
        cp16(aD + off + 32, aS + 8);
        if (PROD) {
            cp16(aD + off + AODD * 4, aS + aOff2);
            cp16(aD + off + AODD * 4 + 32, aS + aOff2 + 8);
        }
        aS += 16;
        if (WT) {
            cp16(bD + off, wS);
            wS += 16;
        } else {
#pragma unroll
            for (int i = 0; i < 4; i++)
                cp4(bD4 + off + i * 4, wN + (long)i * (long)Ndim);
            wN += 16 * (long)Ndim;
        }
    };

    float d[2][4][4];
#pragma unroll
    for (int mt = 0; mt < 2; mt++)
#pragma unroll
        for (int nt = 0; nt < 4; nt++)
#pragma unroll
            for (int q = 0; q < 4; q++) d[mt][nt][q] = 0.f;

    const float* Ap0 = sm + (wm * 32 + g) * 20 + tig;
    const float* Bp0 = sm + BOFF + (wn * 32 + g) * 20 + tig;

    auto compute = [&](int buf) {
        const float* Ap = Ap0 + buf * STG;
        const float* Bp = Bp0 + buf * STG;
#pragma unroll
        for (int kc = 0; kc < 2; kc++) {
            uint32_t ah[2][4], al[2][4], bh[4][2], bl[4][2];
#pragma unroll
            for (int mt = 0; mt < 2; mt++)
#pragma unroll
                for (int i = 0; i < 4; i++) {
                    const int idx = (mt * 16 + (i & 1) * 8) * 20 + kc * 8 + (i >> 1) * 4;
                    float v = Ap[idx];
                    if (PROD) v *= Ap[idx + AODD];
                    const float hi = tf32_hi(v);
                    ah[mt][i] = __float_as_uint(hi);
                    al[mt][i] = __float_as_uint(v - hi);
                }
#pragma unroll
            for (int nt = 0; nt < 4; nt++)
#pragma unroll
                for (int i = 0; i < 2; i++) {
                    const float v = Bp[(nt * 8) * 20 + kc * 8 + i * 4];
                    const float hi = tf32_hi(v);
                    bh[nt][i] = __float_as_uint(hi);
                    bl[nt][i] = __float_as_uint(v - hi);
                }
#pragma unroll
            for (int mt = 0; mt < 2; mt++)
#pragma unroll
                for (int nt = 0; nt < 4; nt++) {
                    MMA_TF32(d[mt][nt], ah[mt], bh[nt]);
                    MMA_TF32(d[mt][nt], ah[mt], bl[nt]);
                    MMA_TF32(d[mt][nt], al[mt], bh[nt]);
                }
        }
    };

    // ---- 3-buffer ring, ONE barrier per stage ----
    issue(0); CP_COMMIT();
    issue(1); CP_COMMIT();

    for (int s = 0; s < NST; s++) {
        if (s == NST - 1) { CP_WAIT0(); } else { CP_WAIT1(); }
        __syncthreads();
        // stage s+2 goes into buffer (s+2)%3 == (s-1)%3, which every thread
        // finished reading before the barrier above -> race-free.
        if (s + 2 < NST) { issue((s + 2) % 3); CP_COMMIT(); }
        compute(s % 3);
    }

    // ---- epilogue (float2 stores; Ndim/ldC always even) ----
#pragma unroll
    for (int mt = 0; mt < 2; mt++) {
        const int r0 = m0 + wm * 32 + mt * 16 + g;
#pragma unroll
        for (int nt = 0; nt < 4; nt++) {
            const int c = n0 + wn * 32 + nt * 8 + 2 * tig;
            if (c + 1 < Ndim) {
#pragma unroll
                for (int half = 0; half < 2; half++) {
                    const long row = r0 + half * 8;
                    float v0 = d[mt][nt][half * 2 + 0];
                    float v1 = d[mt][nt][half * 2 + 1];
                    if (bias) {
                        v0 += __ldg(&bias[c]);
                        v1 += __ldg(&bias[c + 1]);
                    }
                    if (RELU) { v0 = fmaxf(v0, 0.f); v1 = fmaxf(v1, 0.f); }
                    *(float2*)(C + row * ldC + c) = make_float2(v0, v1);
                }
            }
        }
    }
}

extern "C" void kernel_launch(void* const* d_in, const int* in_sizes, int n_in,
                              void* d_out, int out_size)
{
    const float* X    = (const float*)d_in[0];   // (4096,64,64)
    const float* W1   = (const float*)d_in[1];   // (64,128)
    const float* b1   = (const float*)d_in[2];
    const float* W2   = (const float*)d_in[3];   // (128,64)
    const float* b2   = (const float*)d_in[4];
    const float* W3   = (const float*)d_in[5];   // (64,32)
    const float* b3   = (const float*)d_in[6];
    const float* W4   = (const float*)d_in[7];   // (32,32)
    const float* b4   = (const float*)d_in[8];
    const float* P0   = (const float*)d_in[9];   // (64,64,32)
    const float* P1   = (const float*)d_in[10];  // (32,128,64)
    const float* P2   = (const float*)d_in[11];  // (16,256,128)
    const float* P3   = (const float*)d_in[12];  // (8,512,256)
    const float* P4   = (const float*)d_in[13];  // (4,512,512)
    const float* P5   = (const float*)d_in[14];  // (2,512,512)
    const float* Ptop = (const float*)d_in[15];  // (1000,512)
    float* out = (float*)d_out;                  // (4096,1000)

    float *h1, *bufA, *bufB;
    cudaGetSymbolAddress((void**)&h1,  g_h1);
    cudaGetSymbolAddress((void**)&bufA, g_bufA);
    cudaGetSymbolAddress((void**)&bufB, g_bufB);

    const dim3 blk(256);
    const int DYN_N = 3 * 3840 * 4;   // 46080 B (under 48 KB default)
    const int DYN_P = 3 * 6400 * 4;   // 76800 B (needs raised limit)

    cudaFuncSetAttribute(mma_gemm<64,  true, true, false>,
                         cudaFuncAttributeMaxDynamicSharedMemorySize, DYN_P);
    cudaFuncSetAttribute(mma_gemm<128, true, true, false>,
                         cudaFuncAttributeMaxDynamicSharedMemorySize, DYN_P);
    cudaFuncSetAttribute(mma_gemm<256, true, true, false>,
                         cudaFuncAttributeMaxDynamicSharedMemorySize, DYN_P);
    cudaFuncSetAttribute(mma_gemm<512, true, true, false>,
                         cudaFuncAttributeMaxDynamicSharedMemorySize, DYN_P);

    // ---- MLP over 262144 rows ----
    mma_gemm<64, false, false, true><<<dim3(2048, 2, 1), blk, DYN_N>>>(
        X, 64, 0, 0, W1, 0, b1, h1, 128, 0, 128);
    mma_gemm<128, false, false, true><<<dim3(2048, 1, 1), blk, DYN_N>>>(
        h1, 128, 0, 0, W2, 0, b2, bufA, 64, 0, 64);
    mma_gemm<64, false, false, true><<<dim3(2048, 1, 1), blk, DYN_N>>>(
        bufA, 64, 0, 0, W3, 0, b3, h1, 32, 0, 32);
    mma_gemm<32, false, false, false><<<dim3(2048, 1, 1), blk, DYN_N>>>(
        h1, 32, 0, 0, W4, 0, b4, bufB, 32, 0, 32);

    // ---- Leaf: t0[b,j,a] = sum_m P0[j,a,m]*F[b,j,m] -> bufA (B,64,64) ----
    mma_gemm<32, false, true, false><<<dim3(32, 1, 64), blk, DYN_N>>>(
        bufB, 2048, 32, 0, P0, 2048, nullptr, bufA, 4096, 64, 64);

    // ---- Tree levels (pair-product fused into A-tile cp.async) ----
    mma_gemm<64, true, true, false><<<dim3(32, 2, 32), blk, DYN_P>>>(
        bufA, 4096, 128, 64, P1, 128L * 64, nullptr, bufB, 4096, 128, 128);
    mma_gemm<128, true, true, false><<<dim3(32, 4, 16), blk, DYN_P>>>(
        bufB, 4096, 256, 128, P2, 256L * 128, nullptr, bufA, 4096, 256, 256);
    mma_gemm<256, true, true, false><<<dim3(32, 8, 8), blk, DYN_P>>>(
        bufA, 4096, 512, 256, P3, 512L * 256, nullptr, bufB, 4096, 512, 512);
    mma_gemm<512, true, true, false><<<dim3(32, 8, 4), blk, DYN_P>>>(
        bufB, 4096, 1024, 512, P4, 512L * 512, nullptr, bufA, 2048, 512, 512);
    mma_gemm<512, true, true, false><<<dim3(32, 8, 2), blk, DYN_P>>>(
        bufA, 2048, 1024, 512, P5, 512L * 512, nullptr, bufB, 1024, 512, 512);

    // ---- Top: out[b,y] = sum_a Ptop[y,a] * (t5[b,0,a]*t5[b,1,a]) ----
    mma_gemm<512, true, true, false><<<dim3(32, 16, 1), blk, DYN_P>>>(
        bufB, 1024, 0, 512, Ptop, 0, nullptr, out, 1000, 0, 1000);
}

// round 9
// speedup vs baseline: 1.0913x; 1.0913x over previous
#include <cuda_runtime.h>
#include <cstdint>

// ---------------------------------------------------------------------------
// HT model via split-tf32 mma.sync, cp.async double-buffered pipeline.
//   C[j][m,n] = act( sum_k Aop[j][m,k] * W[j][n,k or k,n] + bias[n] )
// Aop = A1 rows or fused pair-product A1*A1[+aOff2] (tree levels, PROD).
// smem: pad-20 linear layout (80B row stride) -> conflict-free cp.async
// stores AND fragment LDS, all offsets compile-time immediates (no index ALU).
// tf32 split x = hi + lo in registers at fragment load; 3 MMAs
// (hi*hi + hi*lo + lo*hi) per m16n8k8 product into fp32 accumulators
// (~2^-21 error/GEMM; 1e-3 budget).
// CTA tile 128xBN (BN=64 or 32), BK=16, 8 warps (4x2), warp tile 32x(BN/2).
// ---------------------------------------------------------------------------

__device__ float g_h1[262144L * 128];
__device__ float g_bufA[262144L * 64];
__device__ float g_bufB[262144L * 64];

static __device__ __forceinline__ uint32_t smem_u32(const void* p) {
    uint32_t a;
    asm("{ .reg .u64 t; cvta.to.shared.u64 t, %1; cvt.u32.u64 %0, t; }" : "=r"(a) : "l"(p));
    return a;
}
static __device__ __forceinline__ void cp16(uint32_t dst, const void* src) {
    asm volatile("cp.async.ca.shared.global [%0], [%1], 16;" :: "r"(dst), "l"(src));
}
static __device__ __forceinline__ void cp4(uint32_t dst, const void* src) {
    asm volatile("cp.async.ca.shared.global [%0], [%1], 4;" :: "r"(dst), "l"(src));
}
#define CP_COMMIT() asm volatile("cp.async.commit_group;" ::: "memory")
#define CP_WAIT1()  asm volatile("cp.async.wait_group 1;" ::: "memory")
#define CP_WAIT0()  asm volatile("cp.async.wait_group 0;" ::: "memory")

static __device__ __forceinline__ float tf32_hi(float x) {
    uint32_t h;
    asm("cvt.rna.tf32.f32 %0, %1;" : "=r"(h) : "f"(x));
    return __uint_as_float(h);
}

#define MMA_TF32(d, a, b)                                                     \
    asm volatile(                                                             \
        "mma.sync.aligned.m16n8k8.row.col.f32.tf32.tf32.f32 "                 \
        "{%0,%1,%2,%3}, {%4,%5,%6,%7}, {%8,%9}, {%0,%1,%2,%3};"               \
        : "+f"((d)[0]), "+f"((d)[1]), "+f"((d)[2]), "+f"((d)[3])              \
        : "r"((a)[0]), "r"((a)[1]), "r"((a)[2]), "r"((a)[3]),                 \
          "r"((b)[0]), "r"((b)[1]))

template <int KDIM, int BN, bool PROD, bool WT, bool RELU>
__global__ void __launch_bounds__(256, 3) mma_gemm(
    const float* __restrict__ A1base, long ldA, long jStrideA, int aOff2,
    const float* __restrict__ Wbase, long jStrideW,
    const float* __restrict__ bias,
    float* __restrict__ Cbase, long ldC, long jStrideC,
    int Ndim)
{
    extern __shared__ float sm[];
    constexpr int NST  = KDIM / 16;
    constexpr int NT   = BN / 16;                 // n-tiles per warp
    constexpr int AODD = 2560;                    // odd-row tile (PROD only)
    constexpr int BOFF = PROD ? 5120 : 2560;
    constexpr int STG  = BOFF + BN * 20;          // floats per stage

    const int j = blockIdx.z;
    const float* A1 = A1base + (long)j * jStrideA;
    const float* W  = Wbase  + (long)j * jStrideW;
    float* C        = Cbase  + (long)j * jStrideC;
    const int m0 = blockIdx.x * 128;
    const int n0 = blockIdx.y * BN;

    const int tid = threadIdx.x;
    const int wid = tid >> 5, lid = tid & 31;
    const int wm = wid >> 1, wn = wid & 1;     // warps: 4 along M x 2 along N
    const int g = lid >> 2, tig = lid & 3;

    const uint32_t smb = smem_u32(sm);

    // ---- per-thread source pointers (advanced by 16 floats per stage) ----
    const int ar = tid & 127;          // A row
    const int ac = tid >> 7;           // chunks ac*4 and ac*4+8
    const float* aS = A1 + (long)(m0 + ar) * ldA + ac * 4;
    const uint32_t aD = smb + (uint32_t)(ar * 20 + ac * 4) * 4;

    const float* wS = nullptr;         // WT path
    uint32_t bD = 0;
    const float* wN = nullptr;         // non-WT path
    uint32_t bD4 = 0;
    const bool bldr = (BN == 64) || (tid < 128);
    if (WT) {
        const int brow = tid & (BN - 1);
        const int bc = (BN == 64) ? (tid >> 6) : ((tid >> 5) & 3);
        int n = n0 + brow; if (n >= Ndim) n = Ndim - 1;
        wS = W + (long)n * KDIM + bc * 4;
        bD = smb + (uint32_t)(BOFF + brow * 20 + bc * 4) * 4;
    } else {
        const int brow = (tid >> 2) & (BN - 1);
        const int k0 = (tid & 3) * 4;
        int n = n0 + brow; if (n >= Ndim) n = Ndim - 1;
        wN = W + (long)k0 * Ndim + n;
        bD4 = smb + (uint32_t)(BOFF + brow * 20 + k0) * 4;
    }

    auto issue = [&](int buf) {
        const uint32_t off = (uint32_t)buf * (STG * 4);
        cp16(aD + off, aS);
        cp16(aD + off + 32, aS + 8);
        if (PROD) {
            cp16(aD + off + AODD * 4, aS + aOff2);
            cp16(aD + off + AODD * 4 + 32, aS + aOff2 + 8);
        }
        aS += 16;
        if (bldr) {
            if (WT) {
                cp16(bD + off, wS);
            } else {
#pragma unroll
                for (int i = 0; i < 4; i++)
                    cp4(bD4 + off + i * 4, wN + (long)i * (long)Ndim);
            }
        }
        if (WT) wS += 16; else wN += 16 * (long)Ndim;
    };

    float d[2][NT][4];
#pragma unroll
    for (int mt = 0; mt < 2; mt++)
#pragma unroll
        for (int nt = 0; nt < NT; nt++)
#pragma unroll
            for (int q = 0; q < 4; q++) d[mt][nt][q] = 0.f;

    const float* Ap0 = sm + (wm * 32 + g) * 20 + tig;
    const float* Bp0 = sm + BOFF + (wn * (BN / 2) + g) * 20 + tig;

    auto compute = [&](int buf) {
        const float* Ap = Ap0 + buf * STG;
        const float* Bp = Bp0 + buf * STG;
#pragma unroll
        for (int kc = 0; kc < 2; kc++) {
            uint32_t ah[2][4], al[2][4], bh[NT][2], bl[NT][2];
#pragma unroll
            for (int mt = 0; mt < 2; mt++)
#pragma unroll
                for (int i = 0; i < 4; i++) {
                    const int idx = (mt * 16 + (i & 1) * 8) * 20 + kc * 8 + (i >> 1) * 4;
                    float v = Ap[idx];
                    if (PROD) v *= Ap[idx + AODD];
                    const float hi = tf32_hi(v);
                    ah[mt][i] = __float_as_uint(hi);
                    al[mt][i] = __float_as_uint(v - hi);
                }
#pragma unroll
            for (int nt = 0; nt < NT; nt++)
#pragma unroll
                for (int i = 0; i < 2; i++) {
                    const float v = Bp[(nt * 8) * 20 + kc * 8 + i * 4];
                    const float hi = tf32_hi(v);
                    bh[nt][i] = __float_as_uint(hi);
                    bl[nt][i] = __float_as_uint(v - hi);
                }
#pragma unroll
            for (int mt = 0; mt < 2; mt++)
#pragma unroll
                for (int nt = 0; nt < NT; nt++) {
                    MMA_TF32(d[mt][nt], ah[mt], bh[nt]);
                    MMA_TF32(d[mt][nt], ah[mt], bl[nt]);
                    MMA_TF32(d[mt][nt], al[mt], bh[nt]);
                }
        }
    };

    // ---- 2-stage double-buffered pipeline ----
    issue(0); CP_COMMIT();
    if (NST > 1) issue(1);
    CP_COMMIT();

    for (int s = 0; s < NST; s++) {
        if (s + 1 < NST) { CP_WAIT1(); } else { CP_WAIT0(); }
        __syncthreads();
        compute(s & 1);
        __syncthreads();
        if (s + 2 < NST) issue(s & 1);
        CP_COMMIT();
    }

    // ---- epilogue (float2 stores; Ndim/ldC always even) ----
#pragma unroll
    for (int mt = 0; mt < 2; mt++) {
        const int r0 = m0 + wm * 32 + mt * 16 + g;
#pragma unroll
        for (int nt = 0; nt < NT; nt++) {
            const int c = n0 + wn * (BN / 2) + nt * 8 + 2 * tig;
            if (c + 1 < Ndim) {
#pragma unroll
                for (int half = 0; half < 2; half++) {
                    const long row = r0 + half * 8;
                    float v0 = d[mt][nt][half * 2 + 0];
                    float v1 = d[mt][nt][half * 2 + 1];
                    if (bias) {
                        v0 += __ldg(&bias[c]);
                        v1 += __ldg(&bias[c + 1]);
                    }
                    if (RELU) { v0 = fmaxf(v0, 0.f); v1 = fmaxf(v1, 0.f); }
                    *(float2*)(C + row * ldC + c) = make_float2(v0, v1);
                }
            }
        }
    }
}

extern "C" void kernel_launch(void* const* d_in, const int* in_sizes, int n_in,
                              void* d_out, int out_size)
{
    const float* X    = (const float*)d_in[0];   // (4096,64,64)
    const float* W1   = (const float*)d_in[1];   // (64,128)
    const float* b1   = (const float*)d_in[2];
    const float* W2   = (const float*)d_in[3];   // (128,64)
    const float* b2   = (const float*)d_in[4];
    const float* W3   = (const float*)d_in[5];   // (64,32)
    const float* b3   = (const float*)d_in[6];
    const float* W4   = (const float*)d_in[7];   // (32,32)
    const float* b4   = (const float*)d_in[8];
    const float* P0   = (const float*)d_in[9];   // (64,64,32)
    const float* P1   = (const float*)d_in[10];  // (32,128,64)
    const float* P2   = (const float*)d_in[11];  // (16,256,128)
    const float* P3   = (const float*)d_in[12];  // (8,512,256)
    const float* P4   = (const float*)d_in[13];  // (4,512,512)
    const float* P5   = (const float*)d_in[14];  // (2,512,512)
    const float* Ptop = (const float*)d_in[15];  // (1000,512)
    float* out = (float*)d_out;                  // (4096,1000)

    float *h1, *bufA, *bufB;
    cudaGetSymbolAddress((void**)&h1,  g_h1);
    cudaGetSymbolAddress((void**)&bufA, g_bufA);
    cudaGetSymbolAddress((void**)&bufB, g_bufB);

    const dim3 blk(256);
    const int DYN_N64 = 2 * (2560 + 64 * 20) * 4;   // 30720 B
    const int DYN_N32 = 2 * (2560 + 32 * 20) * 4;   // 25600 B
    const int DYN_P64 = 2 * (5120 + 64 * 20) * 4;   // 51200 B (raised limit)

    cudaFuncSetAttribute(mma_gemm<64,  64, true, true, false>,
                         cudaFuncAttributeMaxDynamicSharedMemorySize, DYN_P64);
    cudaFuncSetAttribute(mma_gemm<128, 64, true, true, false>,
                         cudaFuncAttributeMaxDynamicSharedMemorySize, DYN_P64);
    cudaFuncSetAttribute(mma_gemm<256, 64, true, true, false>,
                         cudaFuncAttributeMaxDynamicSharedMemorySize, DYN_P64);
    cudaFuncSetAttribute(mma_gemm<512, 64, true, true, false>,
                         cudaFuncAttributeMaxDynamicSharedMemorySize, DYN_P64);

    // ---- MLP over 262144 rows ----
    mma_gemm<64, 64, false, false, true><<<dim3(2048, 2, 1), blk, DYN_N64>>>(
        X, 64, 0, 0, W1, 0, b1, h1, 128, 0, 128);
    mma_gemm<128, 64, false, false, true><<<dim3(2048, 1, 1), blk, DYN_N64>>>(
        h1, 128, 0, 0, W2, 0, b2, bufA, 64, 0, 64);
    mma_gemm<64, 32, false, false, true><<<dim3(2048, 1, 1), blk, DYN_N32>>>(
        bufA, 64, 0, 0, W3, 0, b3, h1, 32, 0, 32);
    mma_gemm<32, 32, false, false, false><<<dim3(2048, 1, 1), blk, DYN_N32>>>(
        h1, 32, 0, 0, W4, 0, b4, bufB, 32, 0, 32);

    // ---- Leaf: t0[b,j,a] = sum_m P0[j,a,m]*F[b,j,m] -> bufA (B,64,64) ----
    mma_gemm<32, 64, false, true, false><<<dim3(32, 1, 64), blk, DYN_N64>>>(
        bufB, 2048, 32, 0, P0, 2048, nullptr, bufA, 4096, 64, 64);

    // ---- Tree levels (pair-product fused into A-tile cp.async) ----
    mma_gemm<64, 64, true, true, false><<<dim3(32, 2, 32), blk, DYN_P64>>>(
        bufA, 4096, 128, 64, P1, 128L * 64, nullptr, bufB, 4096, 128, 128);
    mma_gemm<128, 64, true, true, false><<<dim3(32, 4, 16), blk, DYN_P64>>>(
        bufB, 4096, 256, 128, P2, 256L * 128, nullptr, bufA, 4096, 256, 256);
    mma_gemm<256, 64, true, true, false><<<dim3(32, 8, 8), blk, DYN_P64>>>(
        bufA, 4096, 512, 256, P3, 512L * 256, nullptr, bufB, 4096, 512, 512);
    mma_gemm<512, 64, true, true, false><<<dim3(32, 8, 4), blk, DYN_P64>>>(
        bufB, 4096, 1024, 512, P4, 512L * 512, nullptr, bufA, 2048, 512, 512);
    mma_gemm<512, 64, true, true, false><<<dim3(32, 8, 2), blk, DYN_P64>>>(
        bufA, 2048, 1024, 512, P5, 512L * 512, nullptr, bufB, 1024, 512, 512);

    // ---- Top: out[b,y] = sum_a Ptop[y,a] * (t5[b,0,a]*t5[b,1,a]) ----
    mma_gemm<512, 64, true, true, false><<<dim3(32, 16, 1), blk, DYN_P64>>>(
        bufB, 1024, 0, 512, Ptop, 0, nullptr, out, 1000, 0, 1000);
}

// round 10
// speedup vs baseline: 1.3892x; 1.2729x over previous
#include <cuda_runtime.h>
#include <cstdint>

// ---------------------------------------------------------------------------
// HT model, split-tf32 mma.sync, two benchmark-proven kernel families:
//  * mma_np  (non-PROD; MLP + leaf): pad-20 smem, pointer-bump addressing,
//    template KDIM/BN  -- exact R7/R9 non-PROD kernel (measured fastest).
//  * mma_pr  (PROD; tree levels): XOR-swizzle smem, fused pair-product in
//    the cp.async A path, runtime Kdim -- exact R6 kernel (measured fastest
//    tree configuration).
// Both: tf32 split x = hi + lo in registers; 3 MMAs per product
// (hi*hi + hi*lo + lo*hi) into fp32 accumulators; 2-stage cp.async pipeline.
// ---------------------------------------------------------------------------

__device__ float g_h1[262144L * 128];
__device__ float g_bufA[262144L * 64];
__device__ float g_bufB[262144L * 64];

static __device__ __forceinline__ uint32_t smem_u32(const void* p) {
    uint32_t a;
    asm("{ .reg .u64 t; cvta.to.shared.u64 t, %1; cvt.u32.u64 %0, t; }" : "=r"(a) : "l"(p));
    return a;
}
static __device__ __forceinline__ void cp16(uint32_t dst, const void* src) {
    asm volatile("cp.async.ca.shared.global [%0], [%1], 16;" :: "r"(dst), "l"(src));
}
static __device__ __forceinline__ void cp4(uint32_t dst, const void* src) {
    asm volatile("cp.async.ca.shared.global [%0], [%1], 4;" :: "r"(dst), "l"(src));
}
#define CP_COMMIT() asm volatile("cp.async.commit_group;" ::: "memory")
#define CP_WAIT1()  asm volatile("cp.async.wait_group 1;" ::: "memory")
#define CP_WAIT0()  asm volatile("cp.async.wait_group 0;" ::: "memory")

static __device__ __forceinline__ float tf32_hi(float x) {
    uint32_t h;
    asm("cvt.rna.tf32.f32 %0, %1;" : "=r"(h) : "f"(x));
    return __uint_as_float(h);
}

#define MMA_TF32(d, a, b)                                                     \
    asm volatile(                                                             \
        "mma.sync.aligned.m16n8k8.row.col.f32.tf32.tf32.f32 "                 \
        "{%0,%1,%2,%3}, {%4,%5,%6,%7}, {%8,%9}, {%0,%1,%2,%3};"               \
        : "+f"((d)[0]), "+f"((d)[1]), "+f"((d)[2]), "+f"((d)[3])              \
        : "r"((a)[0]), "r"((a)[1]), "r"((a)[2]), "r"((a)[3]),                 \
          "r"((b)[0]), "r"((b)[1]))

// ===========================================================================
// Non-PROD kernel (MLP + leaf): pad-20 layout, pointer-bump addressing.
// CTA tile 128 x BN, BK=16, 8 warps (4x2), warp tile 32 x (BN/2).
// ===========================================================================
template <int KDIM, int BN, bool WT, bool RELU>
__global__ void __launch_bounds__(256, 3) mma_np(
    const float* __restrict__ A1base, long ldA, long jStrideA,
    const float* __restrict__ Wbase, long jStrideW,
    const float* __restrict__ bias,
    float* __restrict__ Cbase, long ldC, long jStrideC,
    int Ndim)
{
    extern __shared__ float sm[];
    constexpr int NST  = KDIM / 16;
    constexpr int NT   = BN / 16;
    constexpr int BOFF = 2560;
    constexpr int STG  = BOFF + BN * 20;

    const int j = blockIdx.z;
    const float* A1 = A1base + (long)j * jStrideA;
    const float* W  = Wbase  + (long)j * jStrideW;
    float* C        = Cbase  + (long)j * jStrideC;
    const int m0 = blockIdx.x * 128;
    const int n0 = blockIdx.y * BN;

    const int tid = threadIdx.x;
    const int wid = tid >> 5, lid = tid & 31;
    const int wm = wid >> 1, wn = wid & 1;
    const int g = lid >> 2, tig = lid & 3;

    const uint32_t smb = smem_u32(sm);

    const int ar = tid & 127;
    const int ac = tid >> 7;
    const float* aS = A1 + (long)(m0 + ar) * ldA + ac * 4;
    const uint32_t aD = smb + (uint32_t)(ar * 20 + ac * 4) * 4;

    const float* wS = nullptr;
    uint32_t bD = 0;
    const float* wN = nullptr;
    uint32_t bD4 = 0;
    if (WT) {
        const int brow = tid & (BN - 1);
        const int bc = (BN == 64) ? (tid >> 6) : ((tid >> 5) & 3);
        int n = n0 + brow; if (n >= Ndim) n = Ndim - 1;
        wS = W + (long)n * KDIM + bc * 4;
        bD = smb + (uint32_t)(BOFF + brow * 20 + bc * 4) * 4;
    } else {
        const int brow = (tid >> 2) & (BN - 1);
        const int k0 = (tid & 3) * 4;
        int n = n0 + brow; if (n >= Ndim) n = Ndim - 1;
        wN = W + (long)k0 * Ndim + n;
        bD4 = smb + (uint32_t)(BOFF + brow * 20 + k0) * 4;
    }

    auto issue = [&](int buf) {
        const uint32_t off = (uint32_t)buf * (STG * 4);
        cp16(aD + off, aS);
        cp16(aD + off + 32, aS + 8);
        aS += 16;
        if (WT) {
            cp16(bD + off, wS);
            wS += 16;
        } else {
#pragma unroll
            for (int i = 0; i < 4; i++)
                cp4(bD4 + off + i * 4, wN + (long)i * (long)Ndim);
            wN += 16 * (long)Ndim;
        }
    };

    float d[2][NT][4];
#pragma unroll
    for (int mt = 0; mt < 2; mt++)
#pragma unroll
        for (int nt = 0; nt < NT; nt++)
#pragma unroll
            for (int q = 0; q < 4; q++) d[mt][nt][q] = 0.f;

    const float* Ap0 = sm + (wm * 32 + g) * 20 + tig;
    const float* Bp0 = sm + BOFF + (wn * (BN / 2) + g) * 20 + tig;

    auto compute = [&](int buf) {
        const float* Ap = Ap0 + buf * STG;
        const float* Bp = Bp0 + buf * STG;
#pragma unroll
        for (int kc = 0; kc < 2; kc++) {
            uint32_t ah[2][4], al[2][4], bh[NT][2], bl[NT][2];
#pragma unroll
            for (int mt = 0; mt < 2; mt++)
#pragma unroll
                for (int i = 0; i < 4; i++) {
                    const float v = Ap[(mt * 16 + (i & 1) * 8) * 20 + kc * 8 + (i >> 1) * 4];
                    const float hi = tf32_hi(v);
                    ah[mt][i] = __float_as_uint(hi);
                    al[mt][i] = __float_as_uint(v - hi);
                }
#pragma unroll
            for (int nt = 0; nt < NT; nt++)
#pragma unroll
                for (int i = 0; i < 2; i++) {
                    const float v = Bp[(nt * 8) * 20 + kc * 8 + i * 4];
                    const float hi = tf32_hi(v);
                    bh[nt][i] = __float_as_uint(hi);
                    bl[nt][i] = __float_as_uint(v - hi);
                }
#pragma unroll
            for (int mt = 0; mt < 2; mt++)
#pragma unroll
                for (int nt = 0; nt < NT; nt++) {
                    MMA_TF32(d[mt][nt], ah[mt], bh[nt]);
                    MMA_TF32(d[mt][nt], ah[mt], bl[nt]);
                    MMA_TF32(d[mt][nt], al[mt], bh[nt]);
                }
        }
    };

    issue(0); CP_COMMIT();
    if (NST > 1) issue(1);
    CP_COMMIT();

    for (int s = 0; s < NST; s++) {
        if (s + 1 < NST) { CP_WAIT1(); } else { CP_WAIT0(); }
        __syncthreads();
        compute(s & 1);
        __syncthreads();
        if (s + 2 < NST) issue(s & 1);
        CP_COMMIT();
    }

#pragma unroll
    for (int mt = 0; mt < 2; mt++) {
        const int r0 = m0 + wm * 32 + mt * 16 + g;
#pragma unroll
        for (int nt = 0; nt < NT; nt++) {
            const int c = n0 + wn * (BN / 2) + nt * 8 + 2 * tig;
            if (c + 1 < Ndim || c + 1 == Ndim) {
#pragma unroll
                for (int half = 0; half < 2; half++) {
                    const long row = r0 + half * 8;
                    float v0 = d[mt][nt][half * 2 + 0];
                    float v1 = d[mt][nt][half * 2 + 1];
                    if (bias) {
                        v0 += __ldg(&bias[c]);
                        v1 += __ldg(&bias[c + 1]);
                    }
                    if (RELU) { v0 = fmaxf(v0, 0.f); v1 = fmaxf(v1, 0.f); }
                    *(float2*)(C + row * ldC + c) = make_float2(v0, v1);
                }
            }
        }
    }
}

// ===========================================================================
// PROD kernel (tree levels): XOR-swizzle layout, runtime Kdim — exact R6.
// CTA tile 128x64, BK=16, 8 warps (4x2), warp tile 32x32. W is (N,K).
// ===========================================================================
static __device__ __forceinline__ int swz(int row, int k) {
    return row * 16 + ((((k >> 2) ^ ((row >> 1) & 3))) << 2) + (k & 3);
}

__global__ void __launch_bounds__(256, 3) mma_pr(
    const float* __restrict__ A1base, long ldA, long jStrideA, int aOff2,
    const float* __restrict__ Wbase, long jStrideW,
    float* __restrict__ Cbase, long ldC, long jStrideC,
    int Ndim, int Kdim)
{
    extern __shared__ float sm[];
    constexpr int BOFF = 4096;   // A 2048 | Aodd 2048 | B 1024
    constexpr int STG  = 5120;

    const int j = blockIdx.z;
    const float* A1 = A1base + (long)j * jStrideA;
    const float* W  = Wbase  + (long)j * jStrideW;
    float* C        = Cbase  + (long)j * jStrideC;
    const int m0 = blockIdx.x * 128;
    const int n0 = blockIdx.y * 64;

    const int tid = threadIdx.x;
    const int wid = tid >> 5, lid = tid & 31;
    const int wm = wid >> 1, wn = wid & 1;
    const int g = lid >> 2, tig = lid & 3;

    const uint32_t smb = smem_u32(sm);

    float d[2][4][4];
#pragma unroll
    for (int mt = 0; mt < 2; mt++)
#pragma unroll
        for (int nt = 0; nt < 4; nt++)
#pragma unroll
            for (int q = 0; q < 4; q++) d[mt][nt][q] = 0.f;

    const int nst = Kdim >> 4;

    auto issue_stage = [&](int s, int buf) {
        const uint32_t sb = smb + (uint32_t)buf * (STG * 4);
#pragma unroll
        for (int q = 0; q < 2; q++) {
            const int cid = tid + q * 256;
            const int row = cid >> 2, c = cid & 3;
            const uint32_t dst = sb + (uint32_t)(row * 16 + ((c ^ ((row >> 1) & 3)) << 2)) * 4;
            const float* src = A1 + (long)(m0 + row) * ldA + s * 16 + c * 4;
            cp16(dst, src);
            cp16(dst + 2048 * 4, src + aOff2);
        }
        {
            const int row = tid >> 2, c = tid & 3;
            const int n = (n0 + row < Ndim) ? (n0 + row) : (Ndim - 1);
            const uint32_t dst = sb + (uint32_t)(BOFF + row * 16 + ((c ^ ((row >> 1) & 3)) << 2)) * 4;
            cp16(dst, W + (long)n * Kdim + s * 16 + c * 4);
        }
    };

    auto compute = [&](int buf) {
        const float* As = sm + buf * STG;
        const float* Ao = As + 2048;
        const float* Bs = As + BOFF;
#pragma unroll
        for (int kc = 0; kc < 2; kc++) {
            uint32_t ah[2][4], al[2][4], bh[4][2], bl[4][2];
#pragma unroll
            for (int mt = 0; mt < 2; mt++) {
#pragma unroll
                for (int i = 0; i < 4; i++) {
                    const int r = wm * 32 + mt * 16 + g + (i & 1) * 8;
                    const int kk = kc * 8 + tig + (i >> 1) * 4;
                    const int idx = swz(r, kk);
                    float v = As[idx] * Ao[idx];
                    const float hi = tf32_hi(v);
                    ah[mt][i] = __float_as_uint(hi);
                    al[mt][i] = __float_as_uint(v - hi);
                }
            }
#pragma unroll
            for (int nt = 0; nt < 4; nt++) {
#pragma unroll
                for (int i = 0; i < 2; i++) {
                    const int n = wn * 32 + nt * 8 + g;
                    const int kk = kc * 8 + tig + i * 4;
                    const int idx = swz(n, kk);
                    const float v = Bs[idx];
                    const float hi = tf32_hi(v);
                    bh[nt][i] = __float_as_uint(hi);
                    bl[nt][i] = __float_as_uint(v - hi);
                }
            }
#pragma unroll
            for (int mt = 0; mt < 2; mt++)
#pragma unroll
                for (int nt = 0; nt < 4; nt++) {
                    MMA_TF32(d[mt][nt], ah[mt], bh[nt]);
                    MMA_TF32(d[mt][nt], ah[mt], bl[nt]);
                    MMA_TF32(d[mt][nt], al[mt], bh[nt]);
                }
        }
    };

    issue_stage(0, 0);
    CP_COMMIT();
    if (nst > 1) issue_stage(1, 1);
    CP_COMMIT();

    for (int s = 0; s < nst; s++) {
        CP_WAIT1();
        __syncthreads();
        compute(s & 1);
        __syncthreads();
        if (s + 2 < nst) issue_stage(s + 2, s & 1);
        CP_COMMIT();
    }

#pragma unroll
    for (int mt = 0; mt < 2; mt++) {
        const int r0 = m0 + wm * 32 + mt * 16 + g;
#pragma unroll
        for (int nt = 0; nt < 4; nt++) {
            const int c = n0 + wn * 32 + nt * 8 + 2 * tig;
            if (c + 1 < Ndim) {
#pragma unroll
                for (int half = 0; half < 2; half++) {
                    const long row = r0 + half * 8;
                    C[row * ldC + c]     = d[mt][nt][half * 2 + 0];
                    C[row * ldC + c + 1] = d[mt][nt][half * 2 + 1];
                }
            }
        }
    }
}

extern "C" void kernel_launch(void* const* d_in, const int* in_sizes, int n_in,
                              void* d_out, int out_size)
{
    const float* X    = (const float*)d_in[0];   // (4096,64,64)
    const float* W1   = (const float*)d_in[1];   // (64,128)
    const float* b1   = (const float*)d_in[2];
    const float* W2   = (const float*)d_in[3];   // (128,64)
    const float* b2   = (const float*)d_in[4];
    const float* W3   = (const float*)d_in[5];   // (64,32)
    const float* b3   = (const float*)d_in[6];
    const float* W4   = (const float*)d_in[7];   // (32,32)
    const float* b4   = (const float*)d_in[8];
    const float* P0   = (const float*)d_in[9];   // (64,64,32)
    const float* P1   = (const float*)d_in[10];  // (32,128,64)
    const float* P2   = (const float*)d_in[11];  // (16,256,128)
    const float* P3   = (const float*)d_in[12];  // (8,512,256)
    const float* P4   = (const float*)d_in[13];  // (4,512,512)
    const float* P5   = (const float*)d_in[14];  // (2,512,512)
    const float* Ptop = (const float*)d_in[15];  // (1000,512)
    float* out = (float*)d_out;                  // (4096,1000)

    float *h1, *bufA, *bufB;
    cudaGetSymbolAddress((void**)&h1,  g_h1);
    cudaGetSymbolAddress((void**)&bufA, g_bufA);
    cudaGetSymbolAddress((void**)&bufB, g_bufB);

    const dim3 blk(256);
    const int DYN_N64 = 2 * (2560 + 64 * 20) * 4;   // 30720 B
    const int DYN_N32 = 2 * (2560 + 32 * 20) * 4;   // 25600 B
    const int DYN_PR  = 2 * 5120 * 4;               // 40960 B

    // ---- MLP over 262144 rows ----
    mma_np<64, 64, false, true><<<dim3(2048, 2, 1), blk, DYN_N64>>>(
        X, 64, 0, W1, 0, b1, h1, 128, 0, 128);
    mma_np<128, 64, false, true><<<dim3(2048, 1, 1), blk, DYN_N64>>>(
        h1, 128, 0, W2, 0, b2, bufA, 64, 0, 64);
    mma_np<64, 32, false, true><<<dim3(2048, 1, 1), blk, DYN_N32>>>(
        bufA, 64, 0, W3, 0, b3, h1, 32, 0, 32);
    mma_np<32, 32, false, false><<<dim3(2048, 1, 1), blk, DYN_N32>>>(
        h1, 32, 0, W4, 0, b4, bufB, 32, 0, 32);

    // ---- Leaf: t0[b,j,a] = sum_m P0[j,a,m]*F[b,j,m] -> bufA (B,64,64) ----
    mma_np<32, 64, true, false><<<dim3(32, 1, 64), blk, DYN_N64>>>(
        bufB, 2048, 32, P0, 2048, nullptr, bufA, 4096, 64, 64);

    // ---- Tree levels (pair-product fused into A-tile cp.async) ----
    mma_pr<<<dim3(32, 2, 32), blk, DYN_PR>>>(
        bufA, 4096, 128, 64, P1, 128L * 64, bufB, 4096, 128, 128, 64);
    mma_pr<<<dim3(32, 4, 16), blk, DYN_PR>>>(
        bufB, 4096, 256, 128, P2, 256L * 128, bufA, 4096, 256, 256, 128);
    mma_pr<<<dim3(32, 8, 8), blk, DYN_PR>>>(
        bufA, 4096, 512, 256, P3, 512L * 256, bufB, 4096, 512, 512, 256);
    mma_pr<<<dim3(32, 8, 4), blk, DYN_PR>>>(
        bufB, 4096, 1024, 512, P4, 512L * 512, bufA, 2048, 512, 512, 512);
    mma_pr<<<dim3(32, 8, 2), blk, DYN_PR>>>(
        bufA, 2048, 1024, 512, P5, 512L * 512, bufB, 1024, 512, 512, 512);

    // ---- Top: out[b,y] = sum_a Ptop[y,a] * (t5[b,0,a]*t5[b,1,a]) ----
    mma_pr<<<dim3(32, 16, 1), blk, DYN_PR>>>(
        bufB, 1024, 0, 512, Ptop, 0, out, 1000, 0, 1000, 512);
}